// round 10
// baseline (speedup 1.0000x reference)
#include <cuda_runtime.h>

// ---------------------------------------------------------------------------
// SinkhornDistance (degenerate loop):
//   out[b] = sum_{i,j} g(xs_i-ys_j, x_i-y_j), g(d1,d2)=c*exp(-10c), c=d1^2+d2^2
// Separable rank-2 => Chebyshev tensor algebra (n=32 first-kind nodes):
//   out[b] = <S, Wx K Wy^T> + <K, Wx S Wy^T>,
//   Wx[a,c] = sum_i L_a(xs_i) L_c(x_i),  Wy likewise for (ys, y).
// R9: pitch-17 A layout (2-way stores, no XOR), fully unrolled GEMM with
// immediate LDS offsets, packed f32x2 reduction, launch_bounds(256,4) for a
// single 4-blocks/SM wave. Per-batch last-block epilogue as in R8.
// ---------------------------------------------------------------------------

#define NCH    32
#define NPTS   4096
#define NB     8
#define CHUNK  128
#define NCHUNK (NPTS / CHUNK)          // 32
#define BLK_PER_BATCH (2 * NCHUNK)     // 64
#define GRID   (NB * BLK_PER_BATCH)    // 512
#define TPB    256
#define NWARP  (TPB / 32)              // 8
#define PPW    (CHUNK / NWARP)         // 16 points per warp
#define PI     33                      // B pitch (floats), conflict-free
#define API    17                      // A pitch (64-bit pairs): 2-way stores

#define PACK2(out, lo, hi)  asm("mov.b64 %0, {%1, %2};" : "=l"(out) : "f"(lo), "f"(hi))
#define UNPACK2(lo, hi, in) asm("mov.b64 {%0, %1}, %2;" : "=f"(lo), "=f"(hi) : "l"(in))
#define ADD2(out, a, b)     asm("add.rn.f32x2 %0, %1, %2;" : "=l"(out) : "l"(a), "l"(b))
#define FMA2(out, a, b, c)  asm("fma.rn.f32x2 %0, %1, %2, %3;" : "=l"(out) : "l"(a), "l"(b), "l"(c))

__device__ float g_W[NB * 2 * NCH * NCH];   // zero-init; re-zeroed by epilogue
__device__ unsigned int g_cnt[NB];          // per-batch arrivals; reset by owner

struct MomSh {
    unsigned long long A64[CHUNK * API];    // [pt][a-pair], pitch 17  (17408 B)
    float B[CHUNK * PI];                    // [pt][c]                 (16896 B)
    float node[NCH], wt[NCH];
};
struct FinSh {
    float Wx[NCH * PI], Wy[NCH * PI];
    float K [NCH * PI], S [NCH * PI];
    float P [NCH * PI], Q [NCH * PI];
    float red[NWARP];
};

__global__ void __launch_bounds__(TPB, 4) k_fused(
    const float* __restrict__ x,  const float* __restrict__ y,
    const float* __restrict__ xs, const float* __restrict__ ys,
    float* __restrict__ out)
{
    __shared__ __align__(16) union { MomSh m; FinSh f; } sm;
    __shared__ int s_last;

    const int tid   = threadIdx.x;
    const int blk   = blockIdx.x;
    const int chunk = blk & (NCHUNK - 1);
    const int side  = (blk >> 5) & 1;
    const int batch = blk >> 6;

    // ---------------- phase 1: moment contribution ----------------
    if (tid < NCH) {
        float u = (2.0f * tid + 1.0f) / (2.0f * NCH);
        sm.m.node[tid] = cospif(u);
        float s = sinpif(u);
        sm.m.wt[tid] = (tid & 1) ? -s : s;
    }
    __syncthreads();

    const float* A  = side ? ys : xs;       // support coord -> index a
    const float* Bv = side ? y  : x;        // value coord   -> index c
    const int base  = batch * NPTS + chunk * CHUNK;

    // Barycentric Lagrange basis: 256 tasks = 1 per thread
    {
        const int pt    = tid & (CHUNK - 1);
        const int which = tid >> 7;
        float v  = which ? Bv[base + pt] : A[base + pt];
        float xi = 2.0f * v - 1.0f;
        float tv[NCH];
        float ssum = 0.0f;
#pragma unroll
        for (int a = 0; a < NCH; a++) {
            float dd = xi - sm.m.node[a];
            dd = copysignf(fmaxf(fabsf(dd), 1e-12f), dd);
            float q = __fdividef(sm.m.wt[a], dd);
            tv[a] = q;
            ssum += q;
        }
        float inv = __fdividef(1.0f, ssum);
        if (which) {
#pragma unroll
            for (int a = 0; a < NCH; a++) sm.m.B[pt * PI + a] = tv[a] * inv;
        } else {
#pragma unroll
            for (int a2 = 0; a2 < 16; a2++) {
                unsigned long long pr;
                PACK2(pr, tv[2 * a2] * inv, tv[2 * a2 + 1] * inv);
                sm.m.A64[pt * API + a2] = pr;   // pitch-17 => 2-way conflict
            }
        }
    }
    __syncthreads();

    // Outer-product: warp owns 16 points x all 32 c-columns; a-rows packed x2.
    // Fully unrolled: every LDS offset is a compile-time immediate.
    {
        const int w    = tid >> 5;
        const int lane = tid & 31;
        const int p0   = w * PPW;

        unsigned long long acc[NCH / 2];
#pragma unroll
        for (int a2 = 0; a2 < NCH / 2; a2++) acc[a2] = 0ull;

        const unsigned long long* abase = sm.m.A64 + p0 * API;
        const float*              bbase = sm.m.B   + p0 * PI + lane;

#pragma unroll
        for (int i = 0; i < PPW; i++) {
            float bv = bbase[i * PI];                       // coalesced
            unsigned long long bv2;
            PACK2(bv2, bv, bv);
#pragma unroll
            for (int a2 = 0; a2 < NCH / 2; a2++)
                FMA2(acc[a2], abase[i * API + a2], bv2, acc[a2]);  // broadcast
        }

        __syncthreads();
        // Packed reduction: warp w stores its 512 pairs, conflict-free.
        unsigned long long* red64 = reinterpret_cast<unsigned long long*>(&sm);
#pragma unroll
        for (int a2 = 0; a2 < NCH / 2; a2++)
            red64[w * 512 + a2 * 32 + lane] = acc[a2];
        __syncthreads();

        float* Wp = g_W + (batch * 2 + side) * NCH * NCH;
#pragma unroll
        for (int k = 0; k < 2; k++) {
            const int o = tid + 256 * k;       // pair index = a2*32 + lane
            unsigned long long v2 = red64[o];
#pragma unroll
            for (int w2 = 1; w2 < NWARP; w2++)
                ADD2(v2, v2, red64[w2 * 512 + o]);
            float lo, hi;
            UNPACK2(lo, hi, v2);
            const int fo = ((o >> 5) << 6) + (o & 31);     // (2a2)*32 + lane
            atomicAdd(&Wp[fo],      lo);
            atomicAdd(&Wp[fo + 32], hi);
        }
    }

    // ---------------- per-batch last-block election ----------------
    __threadfence();
    __syncthreads();
    if (tid == 0) {
        unsigned prev = atomicAdd(&g_cnt[batch], 1u);
        s_last = (prev == BLK_PER_BATCH - 1);
    }
    __syncthreads();
    if (!s_last) return;

    const int b = batch;
    __threadfence();                            // acquire for g_W reads

    // ---------------- epilogue: contraction for batch b ----------------
    for (int k = tid; k < NCH * NCH; k += TPB) {
        const int a = k >> 5, d = k & 31;
        float wx = __ldcg(&g_W[(b * 2 + 0) * NCH * NCH + k]);
        float wy = __ldcg(&g_W[(b * 2 + 1) * NCH * NCH + k]);
        sm.f.Wx[a * PI + d] = wx;
        sm.f.Wy[a * PI + d] = wy;
        g_W[(b * 2 + 0) * NCH * NCH + k] = 0.0f;   // restore for next replay
        g_W[(b * 2 + 1) * NCH * NCH + k] = 0.0f;
        float pa = cospif((2.0f * a + 1.0f) / (2.0f * NCH));
        float pc = cospif((2.0f * d + 1.0f) / (2.0f * NCH));
        float dd = 0.5f * (pa - pc);
        float c2 = dd * dd;
        float e  = expf(-10.0f * c2);
        sm.f.K[a * PI + d] = e;
        sm.f.S[a * PI + d] = c2 * e;
    }
    __syncthreads();

    // P = Wx*K, Q = Wx*S
    for (int e = tid; e < NCH * NCH; e += TPB) {
        const int a = e >> 5, d = e & 31;
        float p = 0.0f, q = 0.0f;
#pragma unroll
        for (int bb = 0; bb < NCH; bb++) {
            float wv = sm.f.Wx[a * PI + bb];
            p = fmaf(wv, sm.f.K[bb * PI + d], p);
            q = fmaf(wv, sm.f.S[bb * PI + d], q);
        }
        sm.f.P[a * PI + d] = p;
        sm.f.Q[a * PI + d] = q;
    }
    __syncthreads();

    // sum of S.*(P*Wy^T) + K.*(Q*Wy^T)
    float acc = 0.0f;
    for (int e = tid; e < NCH * NCH; e += TPB) {
        const int a = e >> 5, c = e & 31;
        float m = 0.0f, n = 0.0f;
#pragma unroll
        for (int dd = 0; dd < NCH; dd++) {
            float wy = sm.f.Wy[c * PI + dd];
            m = fmaf(sm.f.P[a * PI + dd], wy, m);
            n = fmaf(sm.f.Q[a * PI + dd], wy, n);
        }
        acc += sm.f.S[a * PI + c] * m + sm.f.K[a * PI + c] * n;
    }
#pragma unroll
    for (int off = 16; off > 0; off >>= 1)
        acc += __shfl_xor_sync(0xffffffffu, acc, off);
    if ((tid & 31) == 0) sm.f.red[tid >> 5] = acc;
    __syncthreads();

    if (tid == 0) {
        float v = 0.0f;
#pragma unroll
        for (int w2 = 0; w2 < NWARP; w2++) v += sm.f.red[w2];
        out[b] = v;
        atomicExch(&g_cnt[b], 0u);              // restore counter for replay
    }
}

extern "C" void kernel_launch(void* const* d_in, const int* in_sizes, int n_in,
                              void* d_out, int out_size)
{
    const float* x  = (const float*)d_in[0];
    const float* y  = (const float*)d_in[1];
    const float* xs = (const float*)d_in[2];
    const float* ys = (const float*)d_in[3];
    float* out = (float*)d_out;
    (void)in_sizes; (void)n_in; (void)out_size;

    k_fused<<<GRID, TPB>>>(x, y, xs, ys, out);
}

// round 11
// speedup vs baseline: 1.0813x; 1.0813x over previous
#include <cuda_runtime.h>

// ---------------------------------------------------------------------------
// SinkhornDistance (degenerate loop):
//   out[b] = sum_{i,j} g(xs_i-ys_j, x_i-y_j), g(d1,d2)=c*exp(-10c), c=d1^2+d2^2
// Separable rank-2 => Chebyshev tensor algebra (n=32 first-kind nodes):
//   out[b] = <S, Wx K Wy^T> + <K, Wx S Wy^T>,
//   Wx[a,c] = sum_i L_a(xs_i) L_c(x_i),  Wy likewise for (ys, y).
// R11: deferred-normalization basis (no tv[32] register arrays; unnormalized
// terms streamed to smem, 1/sum folded into the GEMM's B operand). Keeps
// R9's pitch-17 immediate-offset full-unroll GEMM + packed reduction, drops
// the register cap that stalled R9. Per-batch last-block epilogue.
// ---------------------------------------------------------------------------

#define NCH    32
#define NPTS   4096
#define NB     8
#define CHUNK  128
#define NCHUNK (NPTS / CHUNK)          // 32
#define BLK_PER_BATCH (2 * NCHUNK)     // 64
#define GRID   (NB * BLK_PER_BATCH)    // 512
#define TPB    256
#define NWARP  (TPB / 32)              // 8
#define PPW    (CHUNK / NWARP)         // 16 points per warp
#define PI     33                      // B pitch (floats), conflict-free
#define API    17                      // A pitch (64-bit pairs): 2-way stores

#define PACK2(out, lo, hi)  asm("mov.b64 %0, {%1, %2};" : "=l"(out) : "f"(lo), "f"(hi))
#define UNPACK2(lo, hi, in) asm("mov.b64 {%0, %1}, %2;" : "=f"(lo), "=f"(hi) : "l"(in))
#define ADD2(out, a, b)     asm("add.rn.f32x2 %0, %1, %2;" : "=l"(out) : "l"(a), "l"(b))
#define FMA2(out, a, b, c)  asm("fma.rn.f32x2 %0, %1, %2, %3;" : "=l"(out) : "l"(a), "l"(b), "l"(c))

__device__ float g_W[NB * 2 * NCH * NCH];   // zero-init; re-zeroed by epilogue
__device__ unsigned int g_cnt[NB];          // per-batch arrivals; reset by owner

struct MomSh {
    unsigned long long A64[CHUNK * API];    // [pt][a-pair] unnormalized (17408B)
    float B[CHUNK * PI];                    // [pt][c] unnormalized     (16896B)
    float invA[CHUNK], invB[CHUNK];         // per-point 1/sum           (1024B)
    float node[NCH], wt[NCH];
};
struct FinSh {
    float Wx[NCH * PI], Wy[NCH * PI];
    float K [NCH * PI], S [NCH * PI];
    float P [NCH * PI], Q [NCH * PI];
    float red[NWARP];
};

__global__ void __launch_bounds__(TPB) k_fused(
    const float* __restrict__ x,  const float* __restrict__ y,
    const float* __restrict__ xs, const float* __restrict__ ys,
    float* __restrict__ out)
{
    __shared__ __align__(16) union { MomSh m; FinSh f; } sm;
    __shared__ int s_last;

    const int tid   = threadIdx.x;
    const int blk   = blockIdx.x;
    const int chunk = blk & (NCHUNK - 1);
    const int side  = (blk >> 5) & 1;
    const int batch = blk >> 6;

    // ---------------- phase 1: moment contribution ----------------
    if (tid < NCH) {
        float u = (2.0f * tid + 1.0f) / (2.0f * NCH);
        sm.m.node[tid] = cospif(u);
        float s = sinpif(u);
        sm.m.wt[tid] = (tid & 1) ? -s : s;
    }
    __syncthreads();

    const float* A  = side ? ys : xs;       // support coord -> index a
    const float* Bv = side ? y  : x;        // value coord   -> index c
    const int base  = batch * NPTS + chunk * CHUNK;

    // Barycentric basis, UNNORMALIZED, streamed to smem (no register arrays).
    {
        const int pt    = tid & (CHUNK - 1);
        const int which = tid >> 7;
        float v  = which ? Bv[base + pt] : A[base + pt];
        float xi = 2.0f * v - 1.0f;
        float ssum = 0.0f;
        if (which) {
            float* brow = sm.m.B + pt * PI;
#pragma unroll
            for (int a = 0; a < NCH; a++) {
                float dd = xi - sm.m.node[a];
                dd = copysignf(fmaxf(fabsf(dd), 1e-12f), dd);
                float q = __fdividef(sm.m.wt[a], dd);
                brow[a] = q;                       // stride-33: conflict-free
                ssum += q;
            }
            sm.m.invB[pt] = __fdividef(1.0f, ssum);
        } else {
            unsigned long long* arow = sm.m.A64 + pt * API;
#pragma unroll
            for (int a2 = 0; a2 < 16; a2++) {
                float d0 = xi - sm.m.node[2 * a2];
                float d1 = xi - sm.m.node[2 * a2 + 1];
                d0 = copysignf(fmaxf(fabsf(d0), 1e-12f), d0);
                d1 = copysignf(fmaxf(fabsf(d1), 1e-12f), d1);
                float q0 = __fdividef(sm.m.wt[2 * a2],     d0);
                float q1 = __fdividef(sm.m.wt[2 * a2 + 1], d1);
                unsigned long long pr;
                PACK2(pr, q0, q1);
                arow[a2] = pr;                     // pitch-17: 2-way conflict
                ssum += q0 + q1;
            }
            sm.m.invA[pt] = __fdividef(1.0f, ssum);
        }
    }
    __syncthreads();

    // Outer-product: warp owns 16 points x all 32 c-columns; a-rows packed x2.
    // Normalization (invA*invB) folded into the B operand per point.
    {
        const int w    = tid >> 5;
        const int lane = tid & 31;
        const int p0   = w * PPW;

        unsigned long long acc[NCH / 2];
#pragma unroll
        for (int a2 = 0; a2 < NCH / 2; a2++) acc[a2] = 0ull;

        const unsigned long long* abase = sm.m.A64 + p0 * API;
        const float*              bbase = sm.m.B   + p0 * PI + lane;
        const float*              iA    = sm.m.invA + p0;
        const float*              iB    = sm.m.invB + p0;

#pragma unroll
        for (int i = 0; i < PPW; i++) {
            float s  = iA[i] * iB[i];               // broadcast LDS x2
            float bv = bbase[i * PI] * s;           // coalesced LDS
            unsigned long long bv2;
            PACK2(bv2, bv, bv);
#pragma unroll
            for (int a2 = 0; a2 < NCH / 2; a2++)
                FMA2(acc[a2], abase[i * API + a2], bv2, acc[a2]);  // broadcast
        }

        __syncthreads();
        // Packed reduction: warp w stores its 512 pairs, conflict-free.
        unsigned long long* red64 = reinterpret_cast<unsigned long long*>(&sm);
#pragma unroll
        for (int a2 = 0; a2 < NCH / 2; a2++)
            red64[w * 512 + a2 * 32 + lane] = acc[a2];
        __syncthreads();

        float* Wp = g_W + (batch * 2 + side) * NCH * NCH;
#pragma unroll
        for (int k = 0; k < 2; k++) {
            const int o = tid + 256 * k;       // pair index = a2*32 + lane
            unsigned long long v2 = red64[o];
#pragma unroll
            for (int w2 = 1; w2 < NWARP; w2++)
                ADD2(v2, v2, red64[w2 * 512 + o]);
            float lo, hi;
            UNPACK2(lo, hi, v2);
            const int fo = ((o >> 5) << 6) + (o & 31);     // (2a2)*32 + lane
            atomicAdd(&Wp[fo],      lo);
            atomicAdd(&Wp[fo + 32], hi);
        }
    }

    // ---------------- per-batch last-block election ----------------
    __threadfence();
    __syncthreads();
    if (tid == 0) {
        unsigned prev = atomicAdd(&g_cnt[batch], 1u);
        s_last = (prev == BLK_PER_BATCH - 1);
    }
    __syncthreads();
    if (!s_last) return;

    const int b = batch;
    __threadfence();                            // acquire for g_W reads

    // ---------------- epilogue: contraction for batch b ----------------
    for (int k = tid; k < NCH * NCH; k += TPB) {
        const int a = k >> 5, d = k & 31;
        float wx = __ldcg(&g_W[(b * 2 + 0) * NCH * NCH + k]);
        float wy = __ldcg(&g_W[(b * 2 + 1) * NCH * NCH + k]);
        sm.f.Wx[a * PI + d] = wx;
        sm.f.Wy[a * PI + d] = wy;
        g_W[(b * 2 + 0) * NCH * NCH + k] = 0.0f;   // restore for next replay
        g_W[(b * 2 + 1) * NCH * NCH + k] = 0.0f;
        float pa = cospif((2.0f * a + 1.0f) / (2.0f * NCH));
        float pc = cospif((2.0f * d + 1.0f) / (2.0f * NCH));
        float dd = 0.5f * (pa - pc);
        float c2 = dd * dd;
        float e  = expf(-10.0f * c2);
        sm.f.K[a * PI + d] = e;
        sm.f.S[a * PI + d] = c2 * e;
    }
    __syncthreads();

    // P = Wx*K, Q = Wx*S
    for (int e = tid; e < NCH * NCH; e += TPB) {
        const int a = e >> 5, d = e & 31;
        float p = 0.0f, q = 0.0f;
#pragma unroll
        for (int bb = 0; bb < NCH; bb++) {
            float wv = sm.f.Wx[a * PI + bb];
            p = fmaf(wv, sm.f.K[bb * PI + d], p);
            q = fmaf(wv, sm.f.S[bb * PI + d], q);
        }
        sm.f.P[a * PI + d] = p;
        sm.f.Q[a * PI + d] = q;
    }
    __syncthreads();

    // sum of S.*(P*Wy^T) + K.*(Q*Wy^T)
    float acc = 0.0f;
    for (int e = tid; e < NCH * NCH; e += TPB) {
        const int a = e >> 5, c = e & 31;
        float m = 0.0f, n = 0.0f;
#pragma unroll
        for (int dd = 0; dd < NCH; dd++) {
            float wy = sm.f.Wy[c * PI + dd];
            m = fmaf(sm.f.P[a * PI + dd], wy, m);
            n = fmaf(sm.f.Q[a * PI + dd], wy, n);
        }
        acc += sm.f.S[a * PI + c] * m + sm.f.K[a * PI + c] * n;
    }
#pragma unroll
    for (int off = 16; off > 0; off >>= 1)
        acc += __shfl_xor_sync(0xffffffffu, acc, off);
    if ((tid & 31) == 0) sm.f.red[tid >> 5] = acc;
    __syncthreads();

    if (tid == 0) {
        float v = 0.0f;
#pragma unroll
        for (int w2 = 0; w2 < NWARP; w2++) v += sm.f.red[w2];
        out[b] = v;
        atomicExch(&g_cnt[b], 0u);              // restore counter for replay
    }
}

extern "C" void kernel_launch(void* const* d_in, const int* in_sizes, int n_in,
                              void* d_out, int out_size)
{
    const float* x  = (const float*)d_in[0];
    const float* y  = (const float*)d_in[1];
    const float* xs = (const float*)d_in[2];
    const float* ys = (const float*)d_in[3];
    float* out = (float*)d_out;
    (void)in_sizes; (void)n_in; (void)out_size;

    k_fused<<<GRID, TPB>>>(x, y, xs, ys, out);
}